// round 15
// baseline (speedup 1.0000x reference)
#include <cuda_runtime.h>
#include <cstdint>

#define N_AGENTS 8192
#define NPAIRS   (N_AGENTS / 2)           // 4096 float4 slots (2 goals each)
#define AGW      4                        // agents per warp
#define SPLITS   4                        // goal-range splits per agent
#define THREADS  256                      // 8 warps: 2 agent-groups x 4 splits
#define AGB      8                        // agents per block
#define NBLOCKS  (N_AGENTS / AGB)         // 1024
#define PAIRS_PER_SPLIT (NPAIRS / SPLITS) // 1024
#define ITERS    (PAIRS_PER_SPLIT / 64)   // 16 (64 pairs = 128 goals per warp-iter)

// Goals packed NEGATED: slot i = (-x(2i), -y(2i), -x(2i+1), -y(2i+1)).
// Each 8-byte half is a ready-to-use f32x2 operand. 64 KB scratch.
__device__ float4 g_goalsNeg[NPAIRS];

__global__ void __launch_bounds__(256)
pack_goals_kernel(const float* __restrict__ x)
{
    const int g = blockIdx.x * blockDim.x + threadIdx.x;
    if (g < N_AGENTS) {
        const float* gb = x + 3 * N_AGENTS;
        reinterpret_cast<float2*>(g_goalsNeg)[g] =
            make_float2(-gb[3 * g], -gb[3 * g + 1]);
    }
}

// L1 distance via packed math: 1x add.rn.f32x2 + 1x FADD(|lo|,|hi|).
// Bit-identical to fabsf(ax-gx)+fabsf(ay-gy) since gneg holds (-gx,-gy).
__device__ __forceinline__ float hdist(uint64_t axy, uint64_t gneg)
{
    uint64_t s;
    asm("add.rn.f32x2 %0, %1, %2;" : "=l"(s) : "l"(axy), "l"(gneg));
    float lo, hi;
    asm("mov.b64 {%0, %1}, %2;" : "=f"(lo), "=f"(hi) : "l"(s));
    return fabsf(lo) + fabsf(hi);
}

__global__ void __launch_bounds__(THREADS, 6)
rollout_policy_kernel(const float* __restrict__ x,
                      const float* __restrict__ u,
                      float* __restrict__ out)
{
    __shared__ float sd[AGB * SPLITS];
    __shared__ int   si[AGB * SPLITS];

    const int tid   = threadIdx.x;
    const int lane  = tid & 31;
    const int warp  = tid >> 5;              // 0..7
    const int group = warp >> 2;             // 0..1
    const int split = warp & 3;              // 0..3

    const int a0 = blockIdx.x * AGB + group * AGW;

    // Pack each agent's (ax, ay) as f32x2 (x is (2N,3) row-major, cols 0/1).
    uint64_t axy[AGW];
    #pragma unroll
    for (int j = 0; j < AGW; j++) {
        float ax = x[3 * (a0 + j)];
        float ay = x[3 * (a0 + j) + 1];
        asm("mov.b64 %0, {%1, %2};" : "=l"(axy[j]) : "f"(ax), "f"(ay));
    }

    const float INF = __int_as_float(0x7f800000);
    float b[AGW]  = {INF, INF, INF, INF};
    int   itR[AGW] = {0, 0, 0, 0};

    // Iteration it: lane covers pairs p1 = splitBase + 64*it + lane and
    // p2 = p1 + 32 -> goals 2p1, 2p1+1, 2p2, 2p2+1 (ascending per lane).
    const ulonglong2* gp =
        reinterpret_cast<const ulonglong2*>(g_goalsNeg)
        + split * PAIRS_PER_SPLIT + lane;

    #pragma unroll
    for (int it = 0; it < ITERS; it++) {
        const ulonglong2 A = gp[it * 64];        // pair p1: .x=goal0, .y=goal1
        const ulonglong2 B = gp[it * 64 + 32];   // pair p2: .x=goal2, .y=goal3

        #pragma unroll
        for (int j = 0; j < AGW; j++) {
            float d0 = hdist(axy[j], A.x);
            float d1 = hdist(axy[j], A.y);
            float d2 = hdist(axy[j], B.x);
            float d3 = hdist(axy[j], B.y);
            float m  = fminf(fminf(d0, d1), fminf(d2, d3));
            itR[j]   = (m < b[j]) ? it : itR[j];  // first iter achieving new min
            b[j]     = fminf(b[j], m);
        }
    }

    const unsigned mask = 0xffffffffu;

    #pragma unroll
    for (int j = 0; j < AGW; j++) {
        // Rescan recorded iteration: exact first-occurrence index (bit-exact
        // recompute of the same hdist ops).
        const int p1 = split * PAIRS_PER_SPLIT + itR[j] * 64 + lane;
        const ulonglong2 A = gp[itR[j] * 64];
        const ulonglong2 B = gp[itR[j] * 64 + 32];
        float d0 = hdist(axy[j], A.x);
        float d1 = hdist(axy[j], A.y);
        float d2 = hdist(axy[j], B.x);
        float d3 = hdist(axy[j], B.y);
        float best = b[j];
        int bi;
        if      (d0 == best) bi = 2 * p1;
        else if (d1 == best) bi = 2 * p1 + 1;
        else if (d2 == best) bi = 2 * (p1 + 32);
        else                 bi = 2 * (p1 + 32) + 1;

        // Warp lexicographic (dist, idx) reduction.
        #pragma unroll
        for (int off = 16; off; off >>= 1) {
            float od = __shfl_xor_sync(mask, best, off);
            int   oi = __shfl_xor_sync(mask, bi,   off);
            if (od < best || (od == best && oi < bi)) { best = od; bi = oi; }
        }
        if (lane == 0) {
            const int s = (group * AGW + j) * SPLITS + split;
            sd[s] = best;
            si[s] = bi;
        }
    }

    __syncthreads();

    // One thread per agent merges split partials and runs the policy.
    if (tid < AGB) {
        const int base = tid * SPLITS;
        float best = sd[base];
        int   bi   = si[base];
        #pragma unroll
        for (int s = 1; s < SPLITS; s++) {
            float od = sd[base + s];
            int   oi = si[base + s];
            if (od < best || (od == best && oi < bi)) { best = od; bi = oi; }
        }

        const int agent = blockIdx.x * AGB + tid;
        const float ax = x[3 * agent];
        const float ay = x[3 * agent + 1];
        const float* gb = x + 3 * N_AGENTS;
        float dx = gb[3 * bi]     - ax;
        float dy = gb[3 * bi + 1] - ay;

        // probs = [dx>0, dx<0, dy>0, dy<0, (dx==0)&(dy==0)]; cdf = cumsum
        float c0 = (dx > 0.0f) ? 1.0f : 0.0f;
        float c1 = c0 + ((dx < 0.0f) ? 1.0f : 0.0f);
        float c2 = c1 + ((dy > 0.0f) ? 1.0f : 0.0f);
        float c3 = c2 + ((dy < 0.0f) ? 1.0f : 0.0f);
        float c4 = c3 + ((dx == 0.0f && dy == 0.0f) ? 1.0f : 0.0f);

        float t = u[agent] * c4;

        int act = 4;
        if      (c0 >= t) act = 0;
        else if (c1 >= t) act = 1;
        else if (c2 >= t) act = 2;
        else if (c3 >= t) act = 3;

        out[agent] = (float)act;   // output dtype is float32
    }
}

extern "C" void kernel_launch(void* const* d_in, const int* in_sizes, int n_in,
                              void* d_out, int out_size)
{
    // Size-driven binding (element counts): x = 6*N, u = N.
    const float* x = nullptr;
    const float* u = nullptr;
    for (int i = 0; i < n_in; i++) {
        if (in_sizes[i] == 6 * N_AGENTS)      x = (const float*)d_in[i];
        else if (in_sizes[i] == N_AGENTS)     u = (const float*)d_in[i];
    }
    if (!x) x = (const float*)d_in[0];
    if (!u) u = (const float*)d_in[n_in > 1 ? 1 : 0];

    float* out = (float*)d_out;

    pack_goals_kernel<<<N_AGENTS / 256, 256>>>(x);
    rollout_policy_kernel<<<NBLOCKS, THREADS>>>(x, u, out);
    (void)out_size;
}

// round 16
// speedup vs baseline: 3.6026x; 3.6026x over previous
#include <cuda_runtime.h>
#include <cstdint>

#define N_AGENTS 8192
#define NPAIRS   (N_AGENTS / 2)           // 4096 float4 slots (2 goals each)
#define AGW      4                        // agents per warp
#define SPLITS   4                        // goal-range splits per agent
#define THREADS  256                      // 8 warps: 2 agent-groups x 4 splits
#define AGB      8                        // agents per block
#define NBLOCKS  (N_AGENTS / AGB)         // 1024
#define PAIRS_PER_SPLIT (NPAIRS / SPLITS) // 1024
#define ITERS    (PAIRS_PER_SPLIT / 64)   // 16 (64 pairs = 128 goals per warp-iter)

// Goals packed (x0,y0,x1,y1): 2 goals per float4. 64 KB scratch.
__device__ float4 g_goals4[NPAIRS];

__global__ void __launch_bounds__(256)
pack_goals_kernel(const float* __restrict__ x)
{
    const int g = blockIdx.x * blockDim.x + threadIdx.x;
    if (g < N_AGENTS) {
        const float* gb = x + 3 * N_AGENTS;
        reinterpret_cast<float2*>(g_goals4)[g] =
            make_float2(gb[3 * g], gb[3 * g + 1]);
    }
}

__global__ void __launch_bounds__(THREADS, 6)
rollout_policy_kernel(const float* __restrict__ x,
                      const float* __restrict__ u,
                      float* __restrict__ out)
{
    __shared__ float sd[AGB * SPLITS];
    __shared__ int   si[AGB * SPLITS];

    const int tid   = threadIdx.x;
    const int lane  = tid & 31;
    const int warp  = tid >> 5;              // 0..7
    const int group = warp >> 2;             // 0..1
    const int split = warp & 3;              // 0..3

    const int a0 = blockIdx.x * AGB + group * AGW;

    // Agent coords (x is (2N,3) row-major, cols 0/1) — scalar regs only.
    float ax[AGW], ay[AGW];
    #pragma unroll
    for (int j = 0; j < AGW; j++) {
        ax[j] = x[3 * (a0 + j)];
        ay[j] = x[3 * (a0 + j) + 1];
    }

    const float INF = __int_as_float(0x7f800000);
    float b[AGW]   = {INF, INF, INF, INF};
    int   itR[AGW] = {0, 0, 0, 0};

    // Iteration it: lane covers pair slots p1 = base + 64*it + lane and
    // p2 = p1 + 32 -> goals 2p1,2p1+1,2p2,2p2+1 (ascending per lane & iter).
    const float4* gp = g_goals4 + split * PAIRS_PER_SPLIT + lane;

    #pragma unroll 4
    for (int it = 0; it < ITERS; it++) {
        const float4 A = gp[it * 64];
        const float4 B = gp[it * 64 + 32];

        #pragma unroll
        for (int j = 0; j < AGW; j++) {
            float d0 = fabsf(ax[j] - A.x) + fabsf(ay[j] - A.y);
            float d1 = fabsf(ax[j] - A.z) + fabsf(ay[j] - A.w);
            float d2 = fabsf(ax[j] - B.x) + fabsf(ay[j] - B.y);
            float d3 = fabsf(ax[j] - B.z) + fabsf(ay[j] - B.w);
            float m  = fminf(fminf(d0, d1), fminf(d2, d3));
            itR[j]   = (m < b[j]) ? it : itR[j];   // first iter achieving min
            b[j]     = fminf(b[j], m);
        }
    }

    const unsigned mask = 0xffffffffu;

    #pragma unroll
    for (int j = 0; j < AGW; j++) {
        // Rescan recorded iteration: bit-exact recompute, first dist == b[j]
        // in ascending goal order -> exact first-occurrence index.
        const int p1 = split * PAIRS_PER_SPLIT + itR[j] * 64 + lane;
        const float4 A = gp[itR[j] * 64];
        const float4 B = gp[itR[j] * 64 + 32];
        float d0 = fabsf(ax[j] - A.x) + fabsf(ay[j] - A.y);
        float d1 = fabsf(ax[j] - A.z) + fabsf(ay[j] - A.w);
        float d2 = fabsf(ax[j] - B.x) + fabsf(ay[j] - B.y);
        float d3 = fabsf(ax[j] - B.z) + fabsf(ay[j] - B.w);
        float best = b[j];
        int bi;
        if      (d0 == best) bi = 2 * p1;
        else if (d1 == best) bi = 2 * p1 + 1;
        else if (d2 == best) bi = 2 * (p1 + 32);
        else                 bi = 2 * (p1 + 32) + 1;

        // Warp lexicographic (dist, idx) reduction == first-occurrence argmin.
        #pragma unroll
        for (int off = 16; off; off >>= 1) {
            float od = __shfl_xor_sync(mask, best, off);
            int   oi = __shfl_xor_sync(mask, bi,   off);
            if (od < best || (od == best && oi < bi)) { best = od; bi = oi; }
        }
        if (lane == 0) {
            const int s = (group * AGW + j) * SPLITS + split;
            sd[s] = best;
            si[s] = bi;
        }
    }

    __syncthreads();

    // One thread per agent merges split partials and runs the policy.
    if (tid < AGB) {
        const int base = tid * SPLITS;
        float best = sd[base];
        int   bi   = si[base];
        #pragma unroll
        for (int s = 1; s < SPLITS; s++) {
            float od = sd[base + s];
            int   oi = si[base + s];
            if (od < best || (od == best && oi < bi)) { best = od; bi = oi; }
        }

        const int agent = blockIdx.x * AGB + tid;
        const float axs = x[3 * agent];
        const float ays = x[3 * agent + 1];
        const float2 gsel = reinterpret_cast<const float2*>(g_goals4)[bi];
        float dx = gsel.x - axs;
        float dy = gsel.y - ays;

        // probs = [dx>0, dx<0, dy>0, dy<0, (dx==0)&(dy==0)]; cdf = cumsum
        float c0 = (dx > 0.0f) ? 1.0f : 0.0f;
        float c1 = c0 + ((dx < 0.0f) ? 1.0f : 0.0f);
        float c2 = c1 + ((dy > 0.0f) ? 1.0f : 0.0f);
        float c3 = c2 + ((dy < 0.0f) ? 1.0f : 0.0f);
        float c4 = c3 + ((dx == 0.0f && dy == 0.0f) ? 1.0f : 0.0f);

        float t = u[agent] * c4;

        int act = 4;
        if      (c0 >= t) act = 0;
        else if (c1 >= t) act = 1;
        else if (c2 >= t) act = 2;
        else if (c3 >= t) act = 3;

        out[agent] = (float)act;   // output dtype is float32
    }
}

extern "C" void kernel_launch(void* const* d_in, const int* in_sizes, int n_in,
                              void* d_out, int out_size)
{
    // Size-driven binding (element counts): x = 6*N, u = N.
    const float* x = nullptr;
    const float* u = nullptr;
    for (int i = 0; i < n_in; i++) {
        if (in_sizes[i] == 6 * N_AGENTS)      x = (const float*)d_in[i];
        else if (in_sizes[i] == N_AGENTS)     u = (const float*)d_in[i];
    }
    if (!x) x = (const float*)d_in[0];
    if (!u) u = (const float*)d_in[n_in > 1 ? 1 : 0];

    float* out = (float*)d_out;

    pack_goals_kernel<<<N_AGENTS / 256, 256>>>(x);
    rollout_policy_kernel<<<NBLOCKS, THREADS>>>(x, u, out);
    (void)out_size;
}